// round 2
// baseline (speedup 1.0000x reference)
#include <cuda_runtime.h>

#define THETA 0.7f

typedef unsigned long long u64t;

// Effective weights as duplicated f32x2 pairs {w,w}.
// Layout: pair index = ((cin*9 + tap)*8 + u)*8 + ocg, where oc = ocg*8 + u.
__device__ float2 g_Wp2[64 * 9 * 64];

__global__ void prep_w_kernel(const float* __restrict__ W) {
    int idx = blockIdx.x * blockDim.x + threadIdx.x;
    if (idx >= 64 * 64 * 9) return;
    int oc  = idx / 576;
    int rem = idx % 576;
    int cin = rem / 9;
    int tap = rem % 9;
    const float* base = W + oc * 576 + cin * 9;
    float v = base[tap];
    if (tap == 4) {
        float s = 0.f;
#pragma unroll
        for (int t = 0; t < 9; t++) s += base[t];
        v -= THETA * s;
    }
    int ocg = oc >> 3, u = oc & 7;
    g_Wp2[((cin * 9 + tap) * 8 + u) * 8 + ocg] = make_float2(v, v);
}

__device__ __forceinline__ int refl(int i, int n) {
    if (i < 0) i = -i;
    if (i >= n) i = 2 * n - 2 - i;
    return i;
}

__device__ __forceinline__ void ffma2(u64t& d, u64t a, u64t b) {
    asm("fma.rn.f32x2 %0, %1, %2, %0;" : "+l"(d) : "l"(a), "l"(b));
}
__device__ __forceinline__ u64t pack2(float lo, float hi) {
    u64t r;
    asm("mov.b64 %0, {%1, %2};" : "=l"(r) : "f"(lo), "f"(hi));
    return r;
}

// Block: 16x16 spatial tile x 64 oc, one batch. 256 threads.
// ocg = tid&7 -> oc = ocg*8 + u (u=0..7). pxg = tid>>3 -> 2x4 pixel patch.
// Inner product fully in packed fma.rn.f32x2: 288 FFMA2 per cin per thread.
__global__ __launch_bounds__(256, 2)
void conv_kernel(const float* __restrict__ x, float* __restrict__ out) {
    __shared__ float xs[20 * 20];       // raw x tile (reflect indexing)
    __shared__ float ss[18 * 20];       // box3x3 tile, zero outside image
    __shared__ u64t  ws2[9 * 64];       // {w,w} pairs for current cin: [tap][u][ocg]

    const int tx = blockIdx.x, ty = blockIdx.y, b = blockIdx.z;
    const int tid = threadIdx.x;
    const int ocg = tid & 7;
    const int pxg = tid >> 3;
    const int pr0 = (pxg >> 2) * 2;     // 0..14 step 2
    const int pc0 = (pxg & 3) * 4;      // 0,4,8,12

    const int y0 = ty * 16 - 2;
    const int x0 = tx * 16 - 2;

    u64t acc2[8][4];                    // [u][r0p0, r0p1, r1p0, r1p1]
#pragma unroll
    for (int i = 0; i < 8; i++)
#pragma unroll
        for (int j = 0; j < 4; j++) acc2[i][j] = 0ULL;

    const u64t* wg = (const u64t*)g_Wp2;

    for (int cin = 0; cin < 64; cin++) {
        const float* xp = x + (size_t)(b * 64 + cin) * (128 * 128);

        // Load 20x20 x tile with reflect indexing.
#pragma unroll
        for (int k = 0; k < 2; k++) {
            int idx = tid + k * 256;
            if (idx < 400) {
                int r = idx / 20, c = idx % 20;
                xs[r * 20 + c] = xp[refl(y0 + r, 128) * 128 + refl(x0 + c, 128)];
            }
        }
        // Load weight pairs for this cin (576 x 8B, coalesced LDG.64).
        {
            const u64t* wp = wg + cin * 576;
            ws2[tid]       = wp[tid];
            ws2[tid + 256] = wp[tid + 256];
            if (tid < 64) ws2[tid + 512] = wp[tid + 512];
        }
        __syncthreads();

        // 18x18 s tile = box3x3 of reflect-padded x; zero outside image.
#pragma unroll
        for (int k = 0; k < 2; k++) {
            int idx = tid + k * 256;
            if (idx < 324) {
                int rs = idx / 18, cs = idx % 18;
                int sy = y0 + 1 + rs, sx = x0 + 1 + cs;
                float v = 0.f;
                if (sy >= 0 && sy < 128 && sx >= 0 && sx < 128) {
#pragma unroll
                    for (int d = 0; d < 3; d++)
#pragma unroll
                        for (int e = 0; e < 3; e++)
                            v += xs[(rs + d) * 20 + (cs + e)];
                }
                ss[rs * 20 + cs] = v;
            }
        }
        __syncthreads();

        // Packed-FMA core.
#pragma unroll
        for (int ky = 0; ky < 3; ky++) {
            float v0[6], v1[6];
#pragma unroll
            for (int c = 0; c < 6; c++) {
                v0[c] = ss[(pr0 + ky) * 20 + pc0 + c];
                v1[c] = ss[(pr0 + ky + 1) * 20 + pc0 + c];
            }
            u64t p0[5], p1[5];
#pragma unroll
            for (int c = 0; c < 5; c++) {
                p0[c] = pack2(v0[c], v0[c + 1]);
                p1[c] = pack2(v1[c], v1[c + 1]);
            }
#pragma unroll
            for (int kx = 0; kx < 3; kx++) {
                const int tap = ky * 3 + kx;
#pragma unroll
                for (int u = 0; u < 8; u++) {
                    u64t w2 = ws2[(tap * 8 + u) * 8 + ocg];
                    ffma2(acc2[u][0], w2, p0[kx]);
                    ffma2(acc2[u][1], w2, p0[kx + 2]);
                    ffma2(acc2[u][2], w2, p1[kx]);
                    ffma2(acc2[u][3], w2, p1[kx + 2]);
                }
            }
        }
        __syncthreads();
    }

    // Epilogue: packed 8B stores (pair order matches memory order, pc0 even).
    const int r0g = (ty * 16 + pr0) * 128 + tx * 16 + pc0;
#pragma unroll
    for (int u = 0; u < 8; u++) {
        int oc = ocg * 8 + u;
        float* op = out + ((size_t)b * 64 + oc) * (128 * 128);
        *(u64t*)(op + r0g)       = acc2[u][0];
        *(u64t*)(op + r0g + 2)   = acc2[u][1];
        *(u64t*)(op + r0g + 128) = acc2[u][2];
        *(u64t*)(op + r0g + 130) = acc2[u][3];
    }
}

extern "C" void kernel_launch(void* const* d_in, const int* in_sizes, int n_in,
                              void* d_out, int out_size) {
    const float* x = (const float*)d_in[0];   // [16,64,128,128]
    const float* W = (const float*)d_in[1];   // [64,64,3,3]
    float* out = (float*)d_out;               // [16,64,128,128]

    prep_w_kernel<<<(64 * 64 * 9 + 255) / 256, 256>>>(W);

    dim3 grid(128 / 16, 128 / 16, 16);
    conv_kernel<<<grid, 256>>>(x, out);
}

// round 7
// speedup vs baseline: 2.1093x; 2.1093x over previous
#include <cuda_runtime.h>
#include <cstdint>

#define THETA 0.7f

// SMEM (float indices):
//  OFF_B4: current half's weights [9 tap][64 oc][32 cin tf32, XOR-swizzled] = 18432 floats
//  OFF_S4: [3 dx][3 sr][128 q][32 cin tf32, XOR-swizzled]                  = 36864 floats
#define OFF_B4 0
#define OFF_S4 18432
#define SMEM_TOTAL 221184

// W' tf32-rounded, swizzled: [half][tap][oc][cin32 ^ ((oc&7)<<2)]
__device__ float g_Wprep[2 * 9 * 64 * 32];

__device__ __forceinline__ int refl(int i, int n) {
    if (i < 0) i = -i;
    if (i >= n) i = 2 * n - 2 - i;
    return i;
}
__device__ __forceinline__ uint32_t tf32r(float v) {
    uint32_t t;
    asm("cvt.rna.tf32.f32 %0, %1;" : "=r"(t) : "f"(v));
    return t;
}
__device__ __forceinline__ void mma1688(float* d, uint32_t a0, uint32_t a1, uint32_t a2,
                                        uint32_t a3, uint32_t b0, uint32_t b1) {
    asm volatile(
        "mma.sync.aligned.m16n8k8.row.col.f32.tf32.tf32.f32 "
        "{%0,%1,%2,%3},{%4,%5,%6,%7},{%8,%9},{%0,%1,%2,%3};"
        : "+f"(d[0]), "+f"(d[1]), "+f"(d[2]), "+f"(d[3])
        : "r"(a0), "r"(a1), "r"(a2), "r"(a3), "r"(b0), "r"(b1));
}

// W'[oc][cin][tap], center tap -= THETA*sum(taps); tf32-rounded, swizzled.
__global__ void prep_w_kernel(const float* __restrict__ W) {
    int idx = blockIdx.x * blockDim.x + threadIdx.x;
    if (idx >= 64 * 64 * 9) return;
    int oc = idx / 576, rem = idx % 576, cin = rem / 9, tap = rem % 9;
    const float* base = W + oc * 576 + cin * 9;
    float v = base[tap];
    if (tap == 4) {
        float s = 0.f;
#pragma unroll
        for (int t = 0; t < 9; t++) s += base[t];
        v -= THETA * s;
    }
    int dst = (((cin >> 5) * 9 + tap) * 64 + oc) * 32 + ((cin & 31) ^ ((oc & 7) << 2));
    g_Wprep[dst] = __uint_as_float(tf32r(v));
}

// One block per (output row y0, batch b). 256 threads, 8 warps, occ 1.
// Warp tile: 32 M (pixels) x 32 N (oc); full K=576 register-accumulated.
__global__ __launch_bounds__(256, 1)
void conv_mma_kernel(const float* __restrict__ x, float* __restrict__ out) {
    extern __shared__ float sf[];
    uint32_t* us = (uint32_t*)sf;
    const int tid = threadIdx.x, wid = tid >> 5, lane = tid & 31;
    const int warpM = wid & 3, warpN = wid >> 2;
    const int gr = lane >> 2, gc = lane & 3;      // A-frag row/col-in-quad
    const int xorA = gr << 2;
    const int kb = lane & 3, ocq = lane >> 2;     // B-frag k/n lanes
    const int xorB = ocq << 2;
    const int y0 = blockIdx.x, b = blockIdx.y;

    float d[2][4][4];
#pragma unroll
    for (int i = 0; i < 2; i++)
#pragma unroll
        for (int j = 0; j < 4; j++)
#pragma unroll
            for (int r = 0; r < 4; r++) d[i][j][r] = 0.f;

    int xrg[5];
#pragma unroll
    for (int i = 0; i < 5; i++) xrg[i] = refl(y0 - 2 + i, 128);

    for (int half = 0; half < 2; half++) {
        __syncthreads();   // previous half's smem fully consumed

        // Load this half's weights (73728B, float4 coalesced).
        {
            const float4* wsrc = (const float4*)(g_Wprep + half * 18432);
            float4* wdst = (float4*)sf;
            for (int i = tid; i < 4608; i += 256) wdst[i] = wsrc[i];
        }
        // Zero the 6 never-written zero-pad rows (dx=0,q=0 and dx=2,q=127).
        if (tid < 192) {
            int r6 = tid >> 5, cl = tid & 31;
            int R = (r6 < 3) ? r6 * 128 : (3 + r6) * 128 + 127;
            sf[OFF_S4 + R * 32 + cl] = 0.f;
        }

        // Build s = box3x3(reflect-pad x), zero-padded rows, tf32-rounded,
        // 3 dx-shifted copies: R=(dx*3+sr)*128+q holds s[y0-1+sr][q-1+dx][cin].
        for (int u = wid; u < 32; u += 8) {
            const int cg = u & 7, chunk = u >> 3;
            const int c = chunk * 32 + lane;
            const int cm = c ? c - 1 : 1;
            const int cp = (c == 127) ? 126 : c + 1;
            float acc[4][3];
#pragma unroll
            for (int i = 0; i < 4; i++)
#pragma unroll
                for (int sr = 0; sr < 3; sr++) acc[i][sr] = 0.f;
#pragma unroll
            for (int i = 0; i < 4; i++) {
                const float* xp = x + (((size_t)b * 64 + half * 32 + cg * 4 + i) << 14);
#pragma unroll
                for (int xr = 0; xr < 5; xr++) {
                    const float* rp = xp + xrg[xr] * 128;
                    float h = rp[cm] + rp[c] + rp[cp];
                    if (xr < 3)            acc[i][xr]     += h;
                    if (xr >= 1 && xr < 4) acc[i][xr - 1] += h;
                    if (xr >= 2)           acc[i][xr - 2] += h;
                }
            }
#pragma unroll
            for (int sr = 0; sr < 3; sr++) {
                const int vsy = y0 - 1 + sr;
                const bool vr = (vsy >= 0) && (vsy < 128);
                float4 v;
                v.x = __uint_as_float(tf32r(vr ? acc[0][sr] : 0.f));
                v.y = __uint_as_float(tf32r(vr ? acc[1][sr] : 0.f));
                v.z = __uint_as_float(tf32r(vr ? acc[2][sr] : 0.f));
                v.w = __uint_as_float(tf32r(vr ? acc[3][sr] : 0.f));
#pragma unroll
                for (int dx = 0; dx < 3; dx++) {
                    const int q = c + 1 - dx;
                    if (q >= 0 && q < 128) {
                        const int R = (dx * 3 + sr) * 128 + q;
                        *(float4*)(sf + OFF_S4 + R * 32 + ((cg << 2) ^ ((q & 7) << 2))) = v;
                    }
                }
            }
        }
        __syncthreads();

        // MMA mainloop: 9 taps x 4 k-groups of 8. All LDS conflict-free by swizzle.
        for (int dy = 0; dy < 3; dy++) {
#pragma unroll
            for (int dx = 0; dx < 3; dx++) {
                const int abase = OFF_S4 + ((dx * 3 + dy) * 128 + warpM * 32 + gr) * 32;
                const int bbase = OFF_B4 + ((dy * 3 + dx) * 64 + warpN * 32 + ocq) * 32;
#pragma unroll
                for (int j = 0; j < 4; j++) {
                    const int ca0 = (j * 8 + gc) ^ xorA;
                    const int ca1 = (j * 8 + gc + 4) ^ xorA;
                    const int cb0 = (j * 8 + kb) ^ xorB;
                    const int cb1 = (j * 8 + kb + 4) ^ xorB;
                    uint32_t a[2][4];
#pragma unroll
                    for (int mt = 0; mt < 2; mt++) {
                        const int ab = abase + mt * (16 * 32);
                        a[mt][0] = us[ab + ca0];
                        a[mt][1] = us[ab + 8 * 32 + ca0];
                        a[mt][2] = us[ab + ca1];
                        a[mt][3] = us[ab + 8 * 32 + ca1];
                    }
#pragma unroll
                    for (int nt = 0; nt < 4; nt++) {
                        const uint32_t b0 = us[bbase + nt * 256 + cb0];
                        const uint32_t b1 = us[bbase + nt * 256 + cb1];
#pragma unroll
                        for (int mt = 0; mt < 2; mt++)
                            mma1688(d[mt][nt], a[mt][0], a[mt][1], a[mt][2], a[mt][3], b0, b1);
                    }
                }
            }
        }
    }

    // Epilogue: stage D[oc][p] in SMEM (pitch 132, conflict-free), coalesced STG.
    __syncthreads();
#pragma unroll
    for (int mt = 0; mt < 2; mt++)
#pragma unroll
        for (int nt = 0; nt < 4; nt++)
#pragma unroll
            for (int r = 0; r < 4; r++) {
                const int p = warpM * 32 + mt * 16 + gr + ((r >> 1) ? 8 : 0);
                const int oc = warpN * 32 + nt * 8 + 2 * kb + (r & 1);
                sf[oc * 132 + p] = d[mt][nt][r];
            }
    __syncthreads();
#pragma unroll
    for (int it = 0; it < 32; it++) {
        const int idx = it * 256 + tid;
        const int oc = idx >> 7, p = idx & 127;
        out[(((size_t)b * 64 + oc) << 14) + (size_t)y0 * 128 + p] = sf[oc * 132 + p];
    }
}

extern "C" void kernel_launch(void* const* d_in, const int* in_sizes, int n_in,
                              void* d_out, int out_size) {
    const float* x = (const float*)d_in[0];   // [16,64,128,128]
    const float* W = (const float*)d_in[1];   // [64,64,3,3]
    float* out = (float*)d_out;               // [16,64,128,128]

    prep_w_kernel<<<(64 * 64 * 9 + 255) / 256, 256>>>(W);

    cudaFuncSetAttribute(conv_mma_kernel, cudaFuncAttributeMaxDynamicSharedMemorySize,
                         SMEM_TOTAL);
    dim3 grid(128, 16);
    conv_mma_kernel<<<grid, 256, SMEM_TOTAL>>>(x, out);
}